// round 14
// baseline (speedup 1.0000x reference)
#include <cuda_runtime.h>

// Shapes (fixed by the problem)
#define B_    8
#define T_    12
#define N_    512
#define D_    128
#define H_    8
#define HD_   16
#define X_    64            // H_*B_
#define KTOP_ 153           // int(512*0.3)
#define ATTN_ELEMS 201326592ll   // 64*12*512*512

#define FULLMASK 0xffffffffu

// Scratch: projected q,k in split-head layout [x][t][n][hd]; q pre-scaled by 0.25
__device__ float g_qs[X_*T_*N_*HD_];
__device__ float g_ks[X_*T_*N_*HD_];

// ---------------------------------------------------------------------------
// order-preserving float<->uint key transforms (search bounds only)
// ---------------------------------------------------------------------------
__device__ __forceinline__ unsigned flipf(float f) {
    unsigned u = __float_as_uint(f);
    return u ^ ((unsigned)((int)u >> 31) | 0x80000000u);
}
__device__ __forceinline__ float unflipf(unsigned u) {
    unsigned m = 0x80000000u | ~(unsigned)((int)u >> 31);
    return __uint_as_float(u ^ m);
}

// packed f32x2 helpers (Blackwell)
__device__ __forceinline__ unsigned long long pk2(float lo, float hi) {
    unsigned long long d;
    asm("mov.b64 %0, {%1, %2};" : "=l"(d) : "f"(lo), "f"(hi));
    return d;
}
__device__ __forceinline__ float2 up2(unsigned long long v) {
    float2 r;
    asm("mov.b64 {%0, %1}, %2;" : "=f"(r.x), "=f"(r.y) : "l"(v));
    return r;
}
__device__ __forceinline__ unsigned long long fma2(unsigned long long a,
                                                   unsigned long long b,
                                                   unsigned long long c) {
    unsigned long long d;
    asm("fma.rn.f32x2 %0, %1, %2, %3;" : "=l"(d) : "l"(a), "l"(b), "l"(c));
    return d;
}

// ---------------------------------------------------------------------------
// Kernel 1: fused projections. blockIdx.y selects (q|k|v).
// 64 rows per block, 2 rows per thread (r and r+32). q output pre-scaled by
// 0.25 (= 1/sqrt(HD)). Packed fma.rn.f32x2 accumulators over output columns.
// ---------------------------------------------------------------------------
__global__ __launch_bounds__(256, 2) void proj_kernel(
    const float* __restrict__ qin, const float* __restrict__ kin,
    const float* __restrict__ vin,
    const float* __restrict__ Wq, const float* __restrict__ bq,
    const float* __restrict__ Wk, const float* __restrict__ bk,
    const float* __restrict__ Wv, const float* __restrict__ bv,
    float* __restrict__ out_v)
{
    extern __shared__ float sh[];
    float* shW = sh;            // 128*128 floats, swizzled within rows
    float* shA = sh + 16384;    // 64 rows * 129 (padded) floats

    const float* in; const float* W; const float* bias; float* dst; float scale;
    if (blockIdx.y == 0)      { in = qin; W = Wq; bias = bq; dst = g_qs; scale = 0.25f; }
    else if (blockIdx.y == 1) { in = kin; W = Wk; bias = bk; dst = g_ks; scale = 1.0f; }
    else                      { in = vin; W = Wv; bias = bv; dst = out_v; scale = 1.0f; }

    const int tid = threadIdx.x;

    // Load W (permuted): logical col = 16*cg + 4*c + w -> phys word 4*cg + 32*c + w
    for (int i = tid; i < 16384; i += 256) {
        int k = i >> 7, col = i & 127;
        int cg = col >> 4, c = (col >> 2) & 3, w = col & 3;
        shW[k*128 + cg*4 + c*32 + w] = W[i];
    }
    const size_t base_row = (size_t)blockIdx.x * 64;
    for (int i = tid; i < 2048; i += 256) {
        int r = i >> 5, c = i & 31;
        float4 v = __ldg((const float4*)(in + base_row*128) + i);
        float* d = shA + r*129 + c*4;
        d[0] = v.x; d[1] = v.y; d[2] = v.z; d[3] = v.w;
    }
    __syncthreads();

    const int r  = tid >> 3;   // 0..31 : rows r and r+32
    const int cg = tid & 7;    // 0..7  : column group == head index

    unsigned long long ac0[8], ac1[8];
    #pragma unroll
    for (int j = 0; j < 8; j++) {
        unsigned long long b = pk2(__ldg(bias + cg*16 + 2*j), __ldg(bias + cg*16 + 2*j + 1));
        ac0[j] = b; ac1[j] = b;
    }

    const float* arow0 = shA + r*129;
    const float* arow1 = shA + (r+32)*129;
    const float* wbase = shW + cg*4;
    #pragma unroll 4
    for (int k = 0; k < 128; k++) {
        const unsigned long long a0 = pk2(arow0[k], arow0[k]);
        const unsigned long long a1 = pk2(arow1[k], arow1[k]);
        const ulonglong2 w0 = *(const ulonglong2*)(wbase + k*128);
        const ulonglong2 w1 = *(const ulonglong2*)(wbase + k*128 + 32);
        const ulonglong2 w2 = *(const ulonglong2*)(wbase + k*128 + 64);
        const ulonglong2 w3 = *(const ulonglong2*)(wbase + k*128 + 96);
        ac0[0] = fma2(a0, w0.x, ac0[0]);  ac0[1] = fma2(a0, w0.y, ac0[1]);
        ac0[2] = fma2(a0, w1.x, ac0[2]);  ac0[3] = fma2(a0, w1.y, ac0[3]);
        ac0[4] = fma2(a0, w2.x, ac0[4]);  ac0[5] = fma2(a0, w2.y, ac0[5]);
        ac0[6] = fma2(a0, w3.x, ac0[6]);  ac0[7] = fma2(a0, w3.y, ac0[7]);
        ac1[0] = fma2(a1, w0.x, ac1[0]);  ac1[1] = fma2(a1, w0.y, ac1[1]);
        ac1[2] = fma2(a1, w1.x, ac1[2]);  ac1[3] = fma2(a1, w1.y, ac1[3]);
        ac1[4] = fma2(a1, w2.x, ac1[4]);  ac1[5] = fma2(a1, w2.y, ac1[5]);
        ac1[6] = fma2(a1, w3.x, ac1[6]);  ac1[7] = fma2(a1, w3.y, ac1[7]);
    }

    #pragma unroll
    for (int rr = 0; rr < 2; rr++) {
        const int row = (int)base_row + r + rr*32;
        const int b   = row / (T_*N_);
        const int rem = row - b*(T_*N_);
        const int t   = rem / N_;
        const int n   = rem - t*N_;
        const size_t di = ((((size_t)cg*B_ + b)*T_ + t)*N_ + n)*HD_;
        const unsigned long long* a = rr ? ac1 : ac0;
        #pragma unroll
        for (int j = 0; j < 4; j++) {
            const float2 e0 = up2(a[2*j]);
            const float2 e1 = up2(a[2*j+1]);
            *(float4*)(dst + di + 4*j) =
                make_float4(e0.x*scale, e0.y*scale, e1.x*scale, e1.y*scale);
        }
    }
}

// ---------------------------------------------------------------------------
// Exact kth-largest (k = KTOP_) over the 512 values held 16-per-lane in s[].
// Clamped false-position on the flipped-uint grid; iteration 0 probes at a
// caller-supplied statistical guess (clamped into (lo,hi) — exactness is
// unaffected, it is just a bracketing probe). Counts via predicated FADD
// (fma pipe) + REDUX. Exits: c==K (kth = REDUX-min of the top set) or
// width-1 interval. Warp-uniform control flow.
// ---------------------------------------------------------------------------
__device__ __forceinline__ float kth_largest(const float s[16], unsigned lo, unsigned hi,
                                             unsigned tguess)
{
    float clo = (float)N_, chi = 0.f;

    for (int it = 0; it < 16; ++it) {
        if (hi - lo <= 1u) return unflipf(lo);
        unsigned t;
        if (it == 0) {
            t = tguess;
        } else {
            const float f = (clo - (float)KTOP_) / (clo - chi);
            t = lo + (unsigned)((float)(hi - lo) * f);
        }
        const unsigned tmin = lo + 1u, tmax = hi - 1u;
        t = (t < tmin) ? tmin : ((t > tmax) ? tmax : t);
        const float tf = unflipf(t);
        float cf = 0.f;
        #pragma unroll
        for (int j = 0; j < 16; j++)
            if (s[j] >= tf) cf += 1.0f;
        const int c = __reduce_add_sync(FULLMASK, (int)cf);
        if (c == KTOP_) {
            unsigned mk = 0xffffffffu;
            #pragma unroll
            for (int j = 0; j < 16; j++)
                if (s[j] >= tf) mk = umin(mk, flipf(s[j]));
            return unflipf(__reduce_min_sync(FULLMASK, mk));
        }
        if (c > KTOP_) { lo = t; clo = (float)c; }
        else           { hi = t; chi = (float)c; }
    }
    while (hi - lo > 1u) {                          // fallback bisection (rare)
        const unsigned t = lo + ((hi - lo) >> 1);
        const float tf = unflipf(t);
        float cf = 0.f;
        #pragma unroll
        for (int j = 0; j < 16; j++)
            if (s[j] >= tf) cf += 1.0f;
        const int c = __reduce_add_sync(FULLMASK, (int)cf);
        if (c >= KTOP_) lo = t; else hi = t;
    }
    return unflipf(lo);
}

// ---------------------------------------------------------------------------
// Kernel 2: scores + softmax + exact top-k threshold.
// Block: 256 thr (8 warps) = one (x,t), 16 rows (2 rows/warp).
// INTERLEAVED 2-row score sweep: each K smem read feeds BOTH rows (halves
// LDS.128 volume vs row-sequential — the LSU cost round 12 proved binding).
// Search: clamped false-position with a mean+0.31*sigma first probe.
// ---------------------------------------------------------------------------
__global__ __launch_bounds__(256, 3) void attn_kernel(
    const float* __restrict__ adp, float* __restrict__ out)
{
    extern __shared__ float sh[];
    float* Ksh = sh;                       // 512 * 20 floats = 40960 B

    const int xt   = blockIdx.y;           // 0..767
    const int tile = blockIdx.x;           // 0..31 : 16 rows each
    const int tid  = threadIdx.x;
    const int lane = tid & 31;
    const int wid  = tid >> 5;
    const size_t xtbase = (size_t)xt * N_;

    // Stage K tile (512 x 16 floats) into padded smem (row stride 20)
    const float* gk = g_ks + xtbase * HD_;
    for (int i = tid; i < 2048; i += 256) {
        int m = i >> 2, c = i & 3;
        float4 v = __ldg((const float4*)(gk + (size_t)i*4));
        *(float4*)(Ksh + m*20 + c*4) = v;
    }
    __syncthreads();

    const int n0 = tile*16 + wid*2;
    const float* gq = g_qs + (xtbase + n0) * HD_;

    // q packed as (q_d, q_{d+1}) pairs, both rows (8 pairs each)
    unsigned long long qp0[8], qp1[8];
    {
        const float4 a0 = *(const float4*)(gq     );
        const float4 a1 = *(const float4*)(gq +  4);
        const float4 a2 = *(const float4*)(gq +  8);
        const float4 a3 = *(const float4*)(gq + 12);
        qp0[0]=pk2(a0.x,a0.y); qp0[1]=pk2(a0.z,a0.w);
        qp0[2]=pk2(a1.x,a1.y); qp0[3]=pk2(a1.z,a1.w);
        qp0[4]=pk2(a2.x,a2.y); qp0[5]=pk2(a2.z,a2.w);
        qp0[6]=pk2(a3.x,a3.y); qp0[7]=pk2(a3.z,a3.w);
        const float4 b0 = *(const float4*)(gq + 16);
        const float4 b1 = *(const float4*)(gq + 20);
        const float4 b2 = *(const float4*)(gq + 24);
        const float4 b3 = *(const float4*)(gq + 28);
        qp1[0]=pk2(b0.x,b0.y); qp1[1]=pk2(b0.z,b0.w);
        qp1[2]=pk2(b1.x,b1.y); qp1[3]=pk2(b1.z,b1.w);
        qp1[4]=pk2(b2.x,b2.y); qp1[5]=pk2(b2.z,b2.w);
        qp1[6]=pk2(b3.x,b3.y); qp1[7]=pk2(b3.z,b3.w);
    }

    // ---- interleaved score sweep: one K read serves both rows
    float s0[16], s1[16];
    {
        const float* ar0 = adp + (n0    )*N_;
        const float* ar1 = adp + (n0 + 1)*N_;
        #pragma unroll
        for (int j = 0; j < 16; j++) {
            const int m = lane + 32*j;
            const ulonglong2* kp = (const ulonglong2*)(Ksh + m*20);
            const ulonglong2 ka = kp[0];   // d0-3
            const ulonglong2 kb = kp[1];   // d4-7
            const ulonglong2 kc = kp[2];   // d8-11
            const ulonglong2 kd = kp[3];   // d12-15
            unsigned long long a0 = fma2(ka.x, qp0[0], 0ull);
            unsigned long long a1 = fma2(ka.x, qp1[0], 0ull);
            a0 = fma2(ka.y, qp0[1], a0);  a1 = fma2(ka.y, qp1[1], a1);
            a0 = fma2(kb.x, qp0[2], a0);  a1 = fma2(kb.x, qp1[2], a1);
            a0 = fma2(kb.y, qp0[3], a0);  a1 = fma2(kb.y, qp1[3], a1);
            a0 = fma2(kc.x, qp0[4], a0);  a1 = fma2(kc.x, qp1[4], a1);
            a0 = fma2(kc.y, qp0[5], a0);  a1 = fma2(kc.y, qp1[5], a1);
            a0 = fma2(kd.x, qp0[6], a0);  a1 = fma2(kd.x, qp1[6], a1);
            a0 = fma2(kd.y, qp0[7], a0);  a1 = fma2(kd.y, qp1[7], a1);
            const float2 f0 = up2(a0);  s0[j] = (f0.x + f0.y) * __ldg(ar0 + m);
            const float2 f1 = up2(a1);  s1[j] = (f1.x + f1.y) * __ldg(ar1 + m);
        }
    }

    // ---- per row: stats, exact kth, softmax, write (sequential rows)
    #pragma unroll 1
    for (int r = 0; r < 2; r++) {
        const float* s = r ? s1 : s0;

        // lane-local min/max + sums for the statistical first probe
        float mx = s[0], mn = s[0], sm = s[0], sq = s[0]*s[0];
        #pragma unroll
        for (int j = 1; j < 16; j++) {
            const float v = s[j];
            mx = fmaxf(mx, v); mn = fminf(mn, v);
            sm += v; sq = fmaf(v, v, sq);
        }
        const unsigned umx = __reduce_max_sync(FULLMASK, flipf(mx));
        const unsigned umn = __reduce_min_sync(FULLMASK, flipf(mn));
        #pragma unroll
        for (int d = 16; d; d >>= 1) {
            sm += __shfl_xor_sync(FULLMASK, sm, d);
            sq += __shfl_xor_sync(FULLMASK, sq, d);
        }
        const float Mv  = unflipf(umx);
        const float mu  = sm * (1.0f/512.0f);
        const float var = fmaxf(sq * (1.0f/512.0f) - mu*mu, 0.0f);
        const float gss = fmaf(0.312f, __fsqrt_rn(var), mu);  // ~70th pct of gauss*unif

        const float kv = kth_largest(s, umn, umx + 1u, flipf(gss));

        float sum = 0.f;
        float p[16];
        #pragma unroll
        for (int j = 0; j < 16; j++) {
            const float sv = s[j];
            const float pv = __expf(sv - Mv);
            sum += pv;
            p[j] = (sv >= kv) ? pv : -pv;       // sign carries keep flag
        }
        #pragma unroll
        for (int d = 16; d; d >>= 1) sum += __shfl_xor_sync(FULLMASK, sum, d);
        const float inv = 1.0f / sum;

        float* orow = out + (xtbase + n0 + r) * N_;
        #pragma unroll
        for (int j = 0; j < 16; j++)
            orow[lane + 32*j] = fmaxf(p[j], 0.0f) * inv;   // FMNMX, no SEL
    }
}

// ---------------------------------------------------------------------------
extern "C" void kernel_launch(void* const* d_in, const int* in_sizes, int n_in,
                              void* d_out, int out_size)
{
    const float* query = (const float*)d_in[0];
    const float* key   = (const float*)d_in[1];
    const float* value = (const float*)d_in[2];
    const float* adp   = (const float*)d_in[3];
    const float* Wq    = (const float*)d_in[4];
    const float* bq    = (const float*)d_in[5];
    const float* Wk    = (const float*)d_in[6];
    const float* bk    = (const float*)d_in[7];
    const float* Wv    = (const float*)d_in[8];
    const float* bv    = (const float*)d_in[9];

    float* out_attn = (float*)d_out;                 // (64,12,512,512)
    float* out_v    = (float*)d_out + ATTN_ELEMS;    // (64,12,512,16)

    const int proj_smem = (16384 + 64*129) * 4;      // 98560 B
    const int attn_smem = (512*20) * 4;              // 40960 B
    cudaFuncSetAttribute(proj_kernel, cudaFuncAttributeMaxDynamicSharedMemorySize, proj_smem);
    cudaFuncSetAttribute(attn_kernel, cudaFuncAttributeMaxDynamicSharedMemorySize, attn_smem);

    proj_kernel<<<dim3((B_*T_*N_)/64, 3), 256, proj_smem>>>(
        query, key, value, Wq, bq, Wk, bk, Wv, bv, out_v);
    attn_kernel<<<dim3(N_/16, X_*T_), 256, attn_smem>>>(adp, out_attn);
    (void)in_sizes; (void)n_in; (void)out_size;
}

// round 15
// speedup vs baseline: 1.3963x; 1.3963x over previous
#include <cuda_runtime.h>

// Shapes (fixed by the problem)
#define B_    8
#define T_    12
#define N_    512
#define D_    128
#define H_    8
#define HD_   16
#define X_    64            // H_*B_
#define KTOP_ 153           // int(512*0.3)
#define ATTN_ELEMS 201326592ll   // 64*12*512*512

#define FULLMASK 0xffffffffu

// Scratch: projected q,k in split-head layout [x][t][n][hd]; q pre-scaled by 0.25
__device__ float g_qs[X_*T_*N_*HD_];
__device__ float g_ks[X_*T_*N_*HD_];
// Pre-permuted weight matrices (proj smem layout, linear copy at load time)
__device__ float g_Wp[3][D_*D_];

// ---------------------------------------------------------------------------
// order-preserving float<->uint key transforms (search bounds only)
// ---------------------------------------------------------------------------
__device__ __forceinline__ unsigned flipf(float f) {
    unsigned u = __float_as_uint(f);
    return u ^ ((unsigned)((int)u >> 31) | 0x80000000u);
}
__device__ __forceinline__ float unflipf(unsigned u) {
    unsigned m = 0x80000000u | ~(unsigned)((int)u >> 31);
    return __uint_as_float(u ^ m);
}

// packed f32x2 helpers (Blackwell)
__device__ __forceinline__ unsigned long long pk2(float lo, float hi) {
    unsigned long long d;
    asm("mov.b64 %0, {%1, %2};" : "=l"(d) : "f"(lo), "f"(hi));
    return d;
}
__device__ __forceinline__ float2 up2(unsigned long long v) {
    float2 r;
    asm("mov.b64 {%0, %1}, %2;" : "=f"(r.x), "=f"(r.y) : "l"(v));
    return r;
}
__device__ __forceinline__ unsigned long long fma2(unsigned long long a,
                                                   unsigned long long b,
                                                   unsigned long long c) {
    unsigned long long d;
    asm("fma.rn.f32x2 %0, %1, %2, %3;" : "=l"(d) : "l"(a), "l"(b), "l"(c));
    return d;
}

// ---------------------------------------------------------------------------
// Kernel 0: permute W into the proj smem layout once, so proj's staging is a
// straight float4 copy. logical col = 16*cg + 4*c + w -> phys 4*cg + 32*c + w
// ---------------------------------------------------------------------------
__global__ __launch_bounds__(256) void perm_kernel(
    const float* __restrict__ Wq, const float* __restrict__ Wk,
    const float* __restrict__ Wv)
{
    const int which = blockIdx.y;
    const float* W = (which == 0) ? Wq : (which == 1) ? Wk : Wv;
    const int i = blockIdx.x * 256 + threadIdx.x;        // 0..16383
    const int k = i >> 7, col = i & 127;
    const int cg = col >> 4, c = (col >> 2) & 3, w = col & 3;
    g_Wp[which][k*128 + cg*4 + c*32 + w] = W[i];
}

// ---------------------------------------------------------------------------
// Kernel 1: fused projections. blockIdx.y selects (q|k|v).
// 64 rows per block, 2 rows per thread (r and r+32). q output pre-scaled by
// 0.25 (= 1/sqrt(HD)). Packed fma.rn.f32x2 accumulators over output columns.
// ---------------------------------------------------------------------------
__global__ __launch_bounds__(256, 2) void proj_kernel(
    const float* __restrict__ qin, const float* __restrict__ kin,
    const float* __restrict__ vin,
    const float* __restrict__ bq, const float* __restrict__ bk,
    const float* __restrict__ bv,
    float* __restrict__ out_v)
{
    extern __shared__ float sh[];
    float* shW = sh;            // 128*128 floats, pre-permuted
    float* shA = sh + 16384;    // 64 rows * 129 (padded) floats

    const float* in; const float* bias; float* dst; float scale;
    if (blockIdx.y == 0)      { in = qin; bias = bq; dst = g_qs; scale = 0.25f; }
    else if (blockIdx.y == 1) { in = kin; bias = bk; dst = g_ks; scale = 1.0f; }
    else                      { in = vin; bias = bv; dst = out_v; scale = 1.0f; }

    const int tid = threadIdx.x;
    const float* gW = g_Wp[blockIdx.y];

    // W stage: straight float4 copy (already permuted)
    for (int i = tid; i < 4096; i += 256)
        ((float4*)shW)[i] = __ldg((const float4*)gW + i);

    const size_t base_row = (size_t)blockIdx.x * 64;
    for (int i = tid; i < 2048; i += 256) {
        int r = i >> 5, c = i & 31;
        float4 v = __ldg((const float4*)(in + base_row*128) + i);
        float* d = shA + r*129 + c*4;
        d[0] = v.x; d[1] = v.y; d[2] = v.z; d[3] = v.w;
    }
    __syncthreads();

    const int r  = tid >> 3;   // 0..31 : rows r and r+32
    const int cg = tid & 7;    // 0..7  : column group == head index

    unsigned long long ac0[8], ac1[8];
    #pragma unroll
    for (int j = 0; j < 8; j++) {
        unsigned long long b = pk2(__ldg(bias + cg*16 + 2*j), __ldg(bias + cg*16 + 2*j + 1));
        ac0[j] = b; ac1[j] = b;
    }

    const float* arow0 = shA + r*129;
    const float* arow1 = shA + (r+32)*129;
    const float* wbase = shW + cg*4;
    #pragma unroll 4
    for (int k = 0; k < 128; k++) {
        const unsigned long long a0 = pk2(arow0[k], arow0[k]);
        const unsigned long long a1 = pk2(arow1[k], arow1[k]);
        const ulonglong2 w0 = *(const ulonglong2*)(wbase + k*128);
        const ulonglong2 w1 = *(const ulonglong2*)(wbase + k*128 + 32);
        const ulonglong2 w2 = *(const ulonglong2*)(wbase + k*128 + 64);
        const ulonglong2 w3 = *(const ulonglong2*)(wbase + k*128 + 96);
        ac0[0] = fma2(a0, w0.x, ac0[0]);  ac0[1] = fma2(a0, w0.y, ac0[1]);
        ac0[2] = fma2(a0, w1.x, ac0[2]);  ac0[3] = fma2(a0, w1.y, ac0[3]);
        ac0[4] = fma2(a0, w2.x, ac0[4]);  ac0[5] = fma2(a0, w2.y, ac0[5]);
        ac0[6] = fma2(a0, w3.x, ac0[6]);  ac0[7] = fma2(a0, w3.y, ac0[7]);
        ac1[0] = fma2(a1, w0.x, ac1[0]);  ac1[1] = fma2(a1, w0.y, ac1[1]);
        ac1[2] = fma2(a1, w1.x, ac1[2]);  ac1[3] = fma2(a1, w1.y, ac1[3]);
        ac1[4] = fma2(a1, w2.x, ac1[4]);  ac1[5] = fma2(a1, w2.y, ac1[5]);
        ac1[6] = fma2(a1, w3.x, ac1[6]);  ac1[7] = fma2(a1, w3.y, ac1[7]);
    }

    #pragma unroll
    for (int rr = 0; rr < 2; rr++) {
        const int row = (int)base_row + r + rr*32;
        const int b   = row / (T_*N_);
        const int rem = row - b*(T_*N_);
        const int t   = rem / N_;
        const int n   = rem - t*N_;
        const size_t di = ((((size_t)cg*B_ + b)*T_ + t)*N_ + n)*HD_;
        const unsigned long long* a = rr ? ac1 : ac0;
        #pragma unroll
        for (int j = 0; j < 4; j++) {
            const float2 e0 = up2(a[2*j]);
            const float2 e1 = up2(a[2*j+1]);
            *(float4*)(dst + di + 4*j) =
                make_float4(e0.x*scale, e0.y*scale, e1.x*scale, e1.y*scale);
        }
    }
}

// ---------------------------------------------------------------------------
// Exact kth-largest (k = KTOP_) over the 512 values held 16-per-lane in s[].
// DUAL-PROBE search on the flipped-uint grid: each iteration probes the
// false-position point AND the bisection midpoint (guaranteed halving) in
// one pass over s[]; two independent REDUXes overlap their latencies.
// Exits: either count == K (kth = REDUX-min of that top set — exact) or
// width-1 interval. Iteration 0 uses a statistical guess as the FP point.
// ---------------------------------------------------------------------------
__device__ __forceinline__ float kth_largest(const float s[16], unsigned lo, unsigned hi,
                                             unsigned tguess)
{
    float clo = (float)N_, chi = 0.f;

    #pragma unroll 1
    for (int it = 0; it < 34; ++it) {
        if (hi - lo <= 1u) return unflipf(lo);
        unsigned wa;
        if (it == 0) {
            wa = tguess;
        } else {
            const float f = (clo - (float)KTOP_) / (clo - chi);
            wa = lo + (unsigned)((float)(hi - lo) * f);
        }
        const unsigned wb = lo + ((hi - lo) >> 1);
        unsigned t1 = umin(wa, wb), t2 = umax(wa, wb);
        const unsigned a = lo + 1u, b = hi - 1u;
        t1 = (t1 < a) ? a : ((t1 > b) ? b : t1);
        t2 = (t2 < a) ? a : ((t2 > b) ? b : t2);
        const float tf1 = unflipf(t1);
        const float tf2 = unflipf(t2);
        float c1f = 0.f, c2f = 0.f;
        #pragma unroll
        for (int j = 0; j < 16; j++) {
            if (s[j] >= tf1) c1f += 1.0f;
            if (s[j] >= tf2) c2f += 1.0f;
        }
        const int c1 = __reduce_add_sync(FULLMASK, (int)c1f);
        const int c2 = __reduce_add_sync(FULLMASK, (int)c2f);
        if (c1 == KTOP_ || c2 == KTOP_) {
            const float tf = (c1 == KTOP_) ? tf1 : tf2;
            unsigned mk = 0xffffffffu;
            #pragma unroll
            for (int j = 0; j < 16; j++)
                if (s[j] >= tf) mk = umin(mk, flipf(s[j]));
            return unflipf(__reduce_min_sync(FULLMASK, mk));
        }
        if (c2 > KTOP_)      { lo = t2; clo = (float)c2; }
        else if (c1 > KTOP_) { lo = t1; clo = (float)c1; hi = t2; chi = (float)c2; }
        else                 { hi = t1; chi = (float)c1; }
    }
    return unflipf(lo);
}

// ---------------------------------------------------------------------------
// Kernel 2: scores + softmax + exact top-k threshold.
// Block: 256 thr (8 warps) = one (x,t), 16 rows (2 rows/warp).
// ROW-SEQUENTIAL f32x2 score sweeps (empirically optimal: rounds 9/11/12/14).
// ---------------------------------------------------------------------------
__global__ __launch_bounds__(256, 3) void attn_kernel(
    const float* __restrict__ adp, float* __restrict__ out)
{
    extern __shared__ float sh[];
    float* Ksh = sh;                       // 512 * 20 floats = 40960 B

    const int xt   = blockIdx.y;           // 0..767
    const int tile = blockIdx.x;           // 0..31 : 16 rows each
    const int tid  = threadIdx.x;
    const int lane = tid & 31;
    const int wid  = tid >> 5;
    const size_t xtbase = (size_t)xt * N_;

    // Stage K tile (512 x 16 floats) into padded smem (row stride 20)
    const float* gk = g_ks + xtbase * HD_;
    for (int i = tid; i < 2048; i += 256) {
        int m = i >> 2, c = i & 3;
        float4 v = __ldg((const float4*)(gk + (size_t)i*4));
        *(float4*)(Ksh + m*20 + c*4) = v;
    }
    __syncthreads();

    const int n0 = tile*16 + wid*2;
    const float* gq = g_qs + (xtbase + n0) * HD_;

    float s0[16], s1[16];

    // ---- row-sequential score sweeps
    #pragma unroll
    for (int r = 0; r < 2; r++) {
        float* s = r ? s1 : s0;
        const float* q = gq + r*HD_;
        unsigned long long qp[8];
        {
            const float4 a0 = *(const float4*)(q     );
            const float4 a1 = *(const float4*)(q +  4);
            const float4 a2 = *(const float4*)(q +  8);
            const float4 a3 = *(const float4*)(q + 12);
            qp[0]=pk2(a0.x,a0.y); qp[1]=pk2(a0.z,a0.w);
            qp[2]=pk2(a1.x,a1.y); qp[3]=pk2(a1.z,a1.w);
            qp[4]=pk2(a2.x,a2.y); qp[5]=pk2(a2.z,a2.w);
            qp[6]=pk2(a3.x,a3.y); qp[7]=pk2(a3.z,a3.w);
        }
        const float* arow = adp + (n0 + r)*N_;
        #pragma unroll
        for (int j = 0; j < 16; j++) {
            const int m = lane + 32*j;
            const ulonglong2* kp = (const ulonglong2*)(Ksh + m*20);
            const ulonglong2 ka = kp[0];
            const ulonglong2 kb = kp[1];
            const ulonglong2 kc = kp[2];
            const ulonglong2 kd = kp[3];
            unsigned long long a = fma2(ka.x, qp[0], 0ull);
            a = fma2(ka.y, qp[1], a);
            a = fma2(kb.x, qp[2], a);
            a = fma2(kb.y, qp[3], a);
            a = fma2(kc.x, qp[4], a);
            a = fma2(kc.y, qp[5], a);
            a = fma2(kd.x, qp[6], a);
            a = fma2(kd.y, qp[7], a);
            const float2 f = up2(a);
            s[j] = (f.x + f.y) * __ldg(arow + m);
        }
    }

    // ---- per row: stats, exact kth, softmax, write (sequential rows)
    #pragma unroll 1
    for (int r = 0; r < 2; r++) {
        float* s = r ? s1 : s0;

        // lane-local min/max + moments for the statistical first probe
        float mx = s[0], mn = s[0], sm = s[0], sq = s[0]*s[0];
        #pragma unroll
        for (int j = 1; j < 16; j++) {
            const float v = s[j];
            mx = fmaxf(mx, v); mn = fminf(mn, v);
            sm += v; sq = fmaf(v, v, sq);
        }
        const unsigned umx = __reduce_max_sync(FULLMASK, flipf(mx));
        const unsigned umn = __reduce_min_sync(FULLMASK, flipf(mn));
        #pragma unroll
        for (int d = 16; d; d >>= 1) {
            sm += __shfl_xor_sync(FULLMASK, sm, d);
            sq += __shfl_xor_sync(FULLMASK, sq, d);
        }
        const float Mv  = unflipf(umx);
        const float mu  = sm * (1.0f/512.0f);
        const float var = fmaxf(sq * (1.0f/512.0f) - mu*mu, 0.0f);
        const float gss = fmaf(0.312f, __fsqrt_rn(var), mu);  // ~70th pct guess

        const float kv = kth_largest(s, umn, umx + 1u, flipf(gss));

        float sum = 0.f;
        #pragma unroll
        for (int j = 0; j < 16; j++) {
            const float sv = s[j];
            const float pv = __expf(sv - Mv);
            sum += pv;
            s[j] = (sv >= kv) ? pv : -pv;       // sign carries keep flag
        }
        #pragma unroll
        for (int d = 16; d; d >>= 1) sum += __shfl_xor_sync(FULLMASK, sum, d);
        const float inv = 1.0f / sum;

        float* orow = out + (xtbase + n0 + r) * N_;
        #pragma unroll
        for (int j = 0; j < 16; j++)
            orow[lane + 32*j] = fmaxf(s[j], 0.0f) * inv;   // FMNMX, no SEL
    }
}

// ---------------------------------------------------------------------------
extern "C" void kernel_launch(void* const* d_in, const int* in_sizes, int n_in,
                              void* d_out, int out_size)
{
    const float* query = (const float*)d_in[0];
    const float* key   = (const float*)d_in[1];
    const float* value = (const float*)d_in[2];
    const float* adp   = (const float*)d_in[3];
    const float* Wq    = (const float*)d_in[4];
    const float* bq    = (const float*)d_in[5];
    const float* Wk    = (const float*)d_in[6];
    const float* bk    = (const float*)d_in[7];
    const float* Wv    = (const float*)d_in[8];
    const float* bv    = (const float*)d_in[9];

    float* out_attn = (float*)d_out;                 // (64,12,512,512)
    float* out_v    = (float*)d_out + ATTN_ELEMS;    // (64,12,512,16)

    const int proj_smem = (16384 + 64*129) * 4;      // 98560 B
    const int attn_smem = (512*20) * 4;              // 40960 B
    cudaFuncSetAttribute(proj_kernel, cudaFuncAttributeMaxDynamicSharedMemorySize, proj_smem);
    cudaFuncSetAttribute(attn_kernel, cudaFuncAttributeMaxDynamicSharedMemorySize, attn_smem);

    perm_kernel<<<dim3(64, 3), 256>>>(Wq, Wk, Wv);
    proj_kernel<<<dim3((B_*T_*N_)/64, 3), 256, proj_smem>>>(
        query, key, value, bq, bk, bv, out_v);
    attn_kernel<<<dim3(N_/16, X_*T_), 256, attn_smem>>>(adp, out_attn);
    (void)in_sizes; (void)n_in; (void)out_size;
}